// round 15
// baseline (speedup 1.0000x reference)
#include <cuda_runtime.h>
#include <cuda_bf16.h>
#include <math.h>

// ---------------------------------------------------------------------------
// AFEModule, reordered (mix commutes with ifft):
// head(direct DFT of 49 center freqs) -> [fused fft2 + conv] -> ifft (real
// field bf16 hi/lo) -> real channel-mix GEMM (+x epilogue).
// ---------------------------------------------------------------------------

#define NB    8
#define NC    256
#define NIMG  2048
#define HW    128
#define NPIX  16384
#define LDS_  129            // float2 plane stride (conflict-free)
#define PLANE 16512          // 128*129 float2 elements

#define FFT_SMEM (PLANE*8 + 512)

#define CP    134            // conv padded rows
#define CPS   136            // conv padded row stride
#define FC_SMEM (PLANE*8 + CP*CPS*4 + 512)   // fused: sd + pb + twiddles

// Scratch (device globals; allocation-free contract).
__device__ __align__(256) __nv_bfloat16 g_fhi[NIMG * (size_t)NPIX * 2]; // conv out hi, planar
__device__ __align__(256) __nv_bfloat16 g_flo[NIMG * (size_t)NPIX * 2]; // conv out lo, planar
__device__ __align__(256) __nv_bfloat16 g_rfh[NIMG * (size_t)NPIX];     // real field hi (post-ifft)
__device__ __align__(256) __nv_bfloat16 g_rfl[NIMG * (size_t)NPIX];     // real field lo
__device__ __align__(16)  __nv_bfloat16 g_wrhi[NC * NC];
__device__ __align__(16)  __nv_bfloat16 g_wrlo[NC * NC];
__device__ float g_kern[NB * 49];
__device__ float g_center[NB * 49];

__device__ __forceinline__ int brev7(int v) { return (int)(__brev((unsigned)v) >> 25); }

// ---------------------------------------------------------------------------
// 1-D DIF FFT over 128 lines on an interleaved float2 plane.
// Round 1: radix-8 (stages 6,5,4). Round 2: radix-16 (stages 3,2,1,0).
// ---------------------------------------------------------------------------
__device__ void fft_pass(float2* sd, const float* twr, const float* twi,
                         int lineStride, int elemStride)
{
    for (int u = threadIdx.x; u < 2048; u += blockDim.x) {
        const int line = u & 127;
        const int j    = u >> 7;                  // 0..15
        const int o0   = line * lineStride + j * elemStride;
        const int st   = 16 * elemStride;
        float r[8], m[8];
        #pragma unroll
        for (int i = 0; i < 8; ++i) {
            float2 v = sd[o0 + i*st];
            r[i] = v.x; m[i] = v.y;
        }
        #pragma unroll
        for (int i = 0; i < 4; ++i) {
            float tr = r[i] + r[i+4], tm = m[i] + m[i+4];
            float dr = r[i] - r[i+4], dm = m[i] - m[i+4];
            const int e = j + 16*i;
            float wr_ = twr[e], wi_ = twi[e];
            r[i] = tr; m[i] = tm;
            r[i+4] = dr*wr_ - dm*wi_; m[i+4] = dr*wi_ + dm*wr_;
        }
        #pragma unroll
        for (int b2 = 0; b2 < 8; b2 += 4) {
            #pragma unroll
            for (int i = 0; i < 2; ++i) {
                const int a = b2 + i, bb = a + 2;
                float tr = r[a] + r[bb], tm = m[a] + m[bb];
                float dr = r[a] - r[bb], dm = m[a] - m[bb];
                const int e = 2*(j + 16*i);
                float wr_ = twr[e], wi_ = twi[e];
                r[a] = tr; m[a] = tm;
                r[bb] = dr*wr_ - dm*wi_; m[bb] = dr*wi_ + dm*wr_;
            }
        }
        {
            float wr_ = twr[4*j], wi_ = twi[4*j];
            #pragma unroll
            for (int a = 0; a < 8; a += 2) {
                float tr = r[a] + r[a+1], tm = m[a] + m[a+1];
                float dr = r[a] - r[a+1], dm = m[a] - m[a+1];
                r[a] = tr; m[a] = tm;
                r[a+1] = dr*wr_ - dm*wi_; m[a+1] = dr*wi_ + dm*wr_;
            }
        }
        #pragma unroll
        for (int i = 0; i < 8; ++i) sd[o0 + i*st] = make_float2(r[i], m[i]);
    }
    __syncthreads();

    for (int u = threadIdx.x; u < 1024; u += blockDim.x) {
        const int line = u & 127;
        const int g    = u >> 7;                  // 0..7
        const int o0   = line * lineStride + (g << 4) * elemStride;
        float r[16], m[16];
        #pragma unroll
        for (int i = 0; i < 16; ++i) {
            float2 v = sd[o0 + i*elemStride];
            r[i] = v.x; m[i] = v.y;
        }
        #pragma unroll
        for (int k = 0; k < 8; ++k) {
            float tr = r[k] + r[k+8], tm = m[k] + m[k+8];
            float dr = r[k] - r[k+8], dm = m[k] - m[k+8];
            float wr_ = twr[8*k], wi_ = twi[8*k];
            r[k] = tr; m[k] = tm;
            r[k+8] = dr*wr_ - dm*wi_; m[k+8] = dr*wi_ + dm*wr_;
        }
        #pragma unroll
        for (int b2 = 0; b2 < 16; b2 += 8) {
            #pragma unroll
            for (int i = 0; i < 4; ++i) {
                const int a = b2 + i, bb = a + 4;
                float tr = r[a] + r[bb], tm = m[a] + m[bb];
                float dr = r[a] - r[bb], dm = m[a] - m[bb];
                float wr_ = twr[16*i], wi_ = twi[16*i];
                r[a] = tr; m[a] = tm;
                r[bb] = dr*wr_ - dm*wi_; m[bb] = dr*wi_ + dm*wr_;
            }
        }
        #pragma unroll
        for (int b2 = 0; b2 < 16; b2 += 4) {
            #pragma unroll
            for (int i = 0; i < 2; ++i) {
                const int a = b2 + i, bb = a + 2;
                float tr = r[a] + r[bb], tm = m[a] + m[bb];
                float dr = r[a] - r[bb], dm = m[a] - m[bb];
                float wr_ = twr[32*i], wi_ = twi[32*i];
                r[a] = tr; m[a] = tm;
                r[bb] = dr*wr_ - dm*wi_; m[bb] = dr*wi_ + dm*wr_;
            }
        }
        #pragma unroll
        for (int a = 0; a < 16; a += 2) {
            float tr = r[a] + r[a+1], tm = m[a] + m[a+1];
            float dr = r[a] - r[a+1], dm = m[a] - m[a+1];
            r[a] = tr; m[a] = tm; r[a+1] = dr; m[a+1] = dm;
        }
        #pragma unroll
        for (int i = 0; i < 16; ++i) sd[o0 + i*elemStride] = make_float2(r[i], m[i]);
    }
    __syncthreads();
}

// ---------------------------------------------------------------------------
// wr bf16 hi/lo split + zero g_center accumulators.
// ---------------------------------------------------------------------------
__global__ void k_prep(const float* __restrict__ wr)
{
    int i = blockIdx.x * 256 + threadIdx.x;
    float v = wr[i];
    __nv_bfloat16 h = __float2bfloat16(v);
    g_wrhi[i] = h;
    g_wrlo[i] = __float2bfloat16(v - __bfloat162float(h));
    if (i < NB * 49) g_center[i] = 0.0f;
}

// ---------------------------------------------------------------------------
// Head stage 1: direct partial DFT per channel. F(u',v') for u',v' in [-3,3],
// |F|/128 (ortho) accumulated (mean over channels) into g_center via atomics.
// One CTA per channel, 128 threads (one per image row).
// ---------------------------------------------------------------------------
__global__ void __launch_bounds__(128) k_headg(const float* __restrict__ x)
{
    __shared__ float cs[128], sn[128];      // cos(th), sin(-th) for th=2*pi*t/128
    __shared__ float2 gbuf[7][128];         // [v-index][y]

    const int ch  = blockIdx.x;
    const int tid = threadIdx.x;

    {
        float s, c;
        sincosf(-6.283185307179586f * (float)tid / 128.0f, &s, &c);
        cs[tid] = c; sn[tid] = s;
    }
    __syncthreads();

    // Stage A: G(y=tid, v') = sum_x x[y,x] * e^{-2*pi*i*v'*x/128}
    const float4* row4 = (const float4*)(x + (size_t)ch * NPIX + tid * 128);
    float gr[7], gi[7];
    #pragma unroll
    for (int v = 0; v < 7; ++v) { gr[v] = 0.0f; gi[v] = 0.0f; }
    int idx[7];
    #pragma unroll
    for (int v = 0; v < 7; ++v) idx[v] = 0;
    const int step[7] = {125, 126, 127, 0, 1, 2, 3};  // (v'-3) mod 128

    for (int q = 0; q < 32; ++q) {
        float4 vv = row4[q];
        float vals[4] = {vv.x, vv.y, vv.z, vv.w};
        #pragma unroll
        for (int t = 0; t < 4; ++t) {
            float xv = vals[t];
            #pragma unroll
            for (int v = 0; v < 7; ++v) {
                gr[v] = fmaf(xv, cs[idx[v]], gr[v]);
                gi[v] = fmaf(xv, sn[idx[v]], gi[v]);
                idx[v] = (idx[v] + step[v]) & 127;
            }
        }
    }
    #pragma unroll
    for (int v = 0; v < 7; ++v) gbuf[v][tid] = make_float2(gr[v], gi[v]);
    __syncthreads();

    // Stage B: F(p) = sum_y G(y, pc) * e^{-2*pi*i*u'*y/128}, p = pr*7+pc
    if (tid < 49) {
        const int pr = tid / 7, pc = tid % 7;
        const int uu = (pr - 3) & 127;
        float Fr = 0.0f, Fi = 0.0f;
        int e = 0;
        for (int y = 0; y < 128; ++y) {
            float2 g = gbuf[pc][y];
            Fr += g.x * cs[e] - g.y * sn[e];
            Fi += g.x * sn[e] + g.y * cs[e];
            e = (e + uu) & 127;
        }
        float mag = sqrtf(Fr*Fr + Fi*Fi) * (1.0f / 128.0f);
        atomicAdd(&g_center[(ch >> 8) * 49 + tid], mag * (1.0f / 256.0f));
    }
}

// ---------------------------------------------------------------------------
// Head stage 2: MLP + aniso kernel generation. One block per batch.
// ---------------------------------------------------------------------------
__global__ void k_headmlp(const float* __restrict__ w1, const float* __restrict__ b1,
                          const float* __restrict__ w2, const float* __restrict__ b2)
{
    __shared__ float center[49];
    __shared__ float hid[32];
    __shared__ float par[3];
    __shared__ float kk[50];

    const int b = blockIdx.x;
    const int tid = threadIdx.x;   // 64 threads

    if (tid < 49) center[tid] = g_center[b*49 + tid];
    __syncthreads();

    if (tid < 32) {
        float acc = b1[tid];
        for (int p = 0; p < 49; ++p) acc += center[p] * w1[p*32 + tid];
        hid[tid] = fmaxf(acc, 0.0f);
    }
    __syncthreads();
    if (tid < 3) {
        float acc = b2[tid];
        for (int j = 0; j < 32; ++j) acc += hid[j] * w2[j*3 + tid];
        par[tid] = acc;
    }
    __syncthreads();
    if (tid < 49) {
        float theta = atan2f(par[0], par[1]) * 0.5f + 1.5707963267948966f;
        float lam1  = expf(par[2]);
        float lam2  = 1.0f / (lam1 + 1e-8f);
        float ct, st;
        sincosf(theta, &st, &ct);
        float yy = (float)(tid / 7) - 3.0f;
        float xx = (float)(tid % 7) - 3.0f;
        float xr =  xx*ct + yy*st;
        float yr = -xx*st + yy*ct;
        kk[tid] = expf(-(xr*xr / (2.0f*lam1*lam1) + yr*yr / (2.0f*lam2*lam2)));
    }
    __syncthreads();
    if (tid == 0) {
        float s = 0.0f;
        for (int i = 0; i < 49; ++i) s += kk[i];
        kk[49] = s + 1e-8f;
    }
    __syncthreads();
    if (tid < 49) g_kern[b*49 + tid] = kk[tid] / kk[49];
}

// ---------------------------------------------------------------------------
// FUSED forward FFT2 (ortho, two real images packed) + per-plane separation/
// fftshift extraction + 7x7 zero-pad conv. Writes conv output bf16 hi/lo
// (planar, same layout k_ifft expects). Spectra never touch DRAM.
// ---------------------------------------------------------------------------
__global__ void __launch_bounds__(1024) k_fftconv(const float* __restrict__ x)
{
    extern __shared__ float smraw[];
    float2* sd  = (float2*)smraw;                 // PLANE float2
    float*  pb  = smraw + 2*PLANE;                // CP*CPS padded conv plane
    float*  twr = smraw + 2*PLANE + CP*CPS;
    float*  twi = twr + 64;
    __shared__ float kk[49];

    const int ia  = 2*blockIdx.x;
    const int b   = ia >> 8;
    const int tid = threadIdx.x;

    if (tid < 49) kk[tid] = g_kern[b*49 + tid];
    if (tid < 64) {
        float sv, cv;
        sincosf(-6.283185307179586f * (float)tid / 128.0f, &sv, &cv);
        twr[tid] = cv; twi[tid] = sv;
    }
    for (int i = tid; i < CP*CPS; i += 1024) pb[i] = 0.0f;   // borders persist

    const float4* x1 = (const float4*)(x + (size_t)ia * NPIX);
    const float4* x2 = (const float4*)(x + (size_t)(ia+1) * NPIX);
    for (int i = tid; i < NPIX/4; i += 1024) {
        int y = i >> 5, x4 = (i & 31) << 2;
        float4 a = x1[i], c = x2[i];
        float2* d = &sd[y*LDS_ + x4];
        d[0] = make_float2(a.x, c.x);
        d[1] = make_float2(a.y, c.y);
        d[2] = make_float2(a.z, c.z);
        d[3] = make_float2(a.w, c.w);
    }
    __syncthreads();

    fft_pass(sd, twr, twi, LDS_, 1);
    fft_pass(sd, twr, twi, 1, LDS_);

    const float sc = 1.0f / 128.0f;
    const int y0 = (tid >> 4) << 1;   // conv tile: 2 rows x 8 cols
    const int x0 = (tid & 15) << 3;

    #pragma unroll 1
    for (int plane = 0; plane < 4; ++plane) {
        // extraction: separated, shifted plane value into padded buffer
        for (int i = tid; i < NPIX; i += 1024) {
            const int h = i >> 7, w = i & 127;
            const int u = (h + 64) & 127, v = (w + 64) & 127;
            const int un = (128 - u) & 127, vn = (128 - v) & 127;
            float2 W = sd[brev7(u)*LDS_ + brev7(v)];
            float2 N = sd[brev7(un)*LDS_ + brev7(vn)];
            float val;
            if      (plane == 0) val =  0.5f*(W.x + N.x);
            else if (plane == 1) val =  0.5f*(W.y - N.y);
            else if (plane == 2) val =  0.5f*(W.y + N.y);
            else                 val = -0.5f*(W.x - N.x);
            pb[(h+3)*CPS + w + 3] = val * sc;
        }
        __syncthreads();

        // conv 7x7
        float acc[2][8];
        #pragma unroll
        for (int r = 0; r < 2; ++r)
            #pragma unroll
            for (int p = 0; p < 8; ++p) acc[r][p] = 0.0f;

        #pragma unroll
        for (int ri = 0; ri < 8; ++ri) {
            const float* pr = &pb[(y0 + ri)*CPS + x0];
            float buf[16];
            *(float4*)&buf[0]  = *(const float4*)&pr[0];
            *(float4*)&buf[4]  = *(const float4*)&pr[4];
            *(float4*)&buf[8]  = *(const float4*)&pr[8];
            *(float4*)&buf[12] = *(const float4*)&pr[12];
            #pragma unroll
            for (int r = 0; r < 2; ++r) {
                const int dy = ri - r;
                if (dy < 0 || dy > 6) continue;
                #pragma unroll
                for (int dx = 0; dx < 7; ++dx) {
                    float w = kk[dy*7 + dx];
                    #pragma unroll
                    for (int p = 0; p < 8; ++p)
                        acc[r][p] = fmaf(w, buf[dx+p], acc[r][p]);
                }
            }
        }

        __nv_bfloat16* dh = g_fhi + (size_t)(2*ia + plane) * NPIX;
        __nv_bfloat16* dl = g_flo + (size_t)(2*ia + plane) * NPIX;
        #pragma unroll
        for (int r = 0; r < 2; ++r) {
            const int o = (y0 + r)*128 + x0;
            uint4 ph, pl;
            __nv_bfloat16* hp = (__nv_bfloat16*)&ph;
            __nv_bfloat16* lp = (__nv_bfloat16*)&pl;
            #pragma unroll
            for (int p = 0; p < 8; ++p) {
                __nv_bfloat16 h = __float2bfloat16(acc[r][p]);
                hp[p] = h;
                lp[p] = __float2bfloat16(acc[r][p] - __bfloat162float(h));
            }
            *(uint4*)&dh[o] = ph;
            *(uint4*)&dl[o] = pl;
        }
        __syncthreads();   // conv reads done before next extraction overwrites pb
    }
}

// ---------------------------------------------------------------------------
// Inverse FFT2 (ortho) of TWO channels of conv output (Hermitian-projected,
// packed; dedup form — each bf16 read exactly once). Emits real field bf16.
// ---------------------------------------------------------------------------
__global__ void k_ifft()
{
    extern __shared__ float smraw[];
    float2* sd  = (float2*)smraw;
    float*  twr = smraw + 2*PLANE;
    float*  twi = twr + 64;

    const int ia = 2*blockIdx.x;
    const __nv_bfloat16* C1rh = g_fhi + (size_t)(2*ia + 0)*NPIX;
    const __nv_bfloat16* C1ih = g_fhi + (size_t)(2*ia + 1)*NPIX;
    const __nv_bfloat16* C2rh = g_fhi + (size_t)(2*ia + 2)*NPIX;
    const __nv_bfloat16* C2ih = g_fhi + (size_t)(2*ia + 3)*NPIX;
    const __nv_bfloat16* C1rl = g_flo + (size_t)(2*ia + 0)*NPIX;
    const __nv_bfloat16* C1il = g_flo + (size_t)(2*ia + 1)*NPIX;
    const __nv_bfloat16* C2rl = g_flo + (size_t)(2*ia + 2)*NPIX;
    const __nv_bfloat16* C2il = g_flo + (size_t)(2*ia + 3)*NPIX;

    for (int t = threadIdx.x; t < 64; t += blockDim.x) {
        float sv, cv;
        sincosf(6.283185307179586f * (float)t / 128.0f, &sv, &cv);
        twr[t] = cv; twi[t] = sv;
    }
    for (int i = threadIdx.x; i < NPIX; i += blockDim.x) {
        const int u = i >> 7, v = i & 127;
        const int un = (128 - u) & 127, vn = (128 - v) & 127;
        const int j = un*128 + vn;
        if (i > j) continue;
        const int si = ((u+64)&127)*128 + ((v+64)&127);
        const int sj = ((un+64)&127)*128 + ((vn+64)&127);
        float A1r = __bfloat162float(C1rh[si]) + __bfloat162float(C1rl[si]);
        float B1r = __bfloat162float(C1rh[sj]) + __bfloat162float(C1rl[sj]);
        float A1i = __bfloat162float(C1ih[si]) + __bfloat162float(C1il[si]);
        float B1i = __bfloat162float(C1ih[sj]) + __bfloat162float(C1il[sj]);
        float A2r = __bfloat162float(C2rh[si]) + __bfloat162float(C2rl[si]);
        float B2r = __bfloat162float(C2rh[sj]) + __bfloat162float(C2rl[sj]);
        float A2i = __bfloat162float(C2ih[si]) + __bfloat162float(C2il[si]);
        float B2i = __bfloat162float(C2ih[sj]) + __bfloat162float(C2il[sj]);
        float r1 = 0.5f*(A1r + B1r), m1 = 0.5f*(A1i - B1i);
        float r2 = 0.5f*(A2r + B2r), m2 = 0.5f*(A2i - B2i);
        sd[u*LDS_ + v]   = make_float2(r1 - m2, m1 + r2);
        sd[un*LDS_ + vn] = make_float2(r1 + m2, r2 - m1);
    }
    __syncthreads();

    fft_pass(sd, twr, twi, LDS_, 1);
    fft_pass(sd, twr, twi, 1, LDS_);

    __nv_bfloat16* h1 = g_rfh + (size_t)ia * NPIX;
    __nv_bfloat16* l1 = g_rfl + (size_t)ia * NPIX;
    __nv_bfloat16* h2 = h1 + NPIX;
    __nv_bfloat16* l2 = l1 + NPIX;
    const float sc = 1.0f / 128.0f;
    for (int i = threadIdx.x; i < NPIX; i += blockDim.x) {
        int u = i >> 7, v = i & 127;
        float2 s = sd[brev7(u)*LDS_ + brev7(v)];
        float v1 = s.x * sc, v2 = s.y * sc;
        __nv_bfloat16 b1 = __float2bfloat16(v1);
        __nv_bfloat16 b2 = __float2bfloat16(v2);
        h1[i] = b1;  l1[i] = __float2bfloat16(v1 - __bfloat162float(b1));
        h2[i] = b2;  l2[i] = __float2bfloat16(v2 - __bfloat162float(b2));
    }
}

// ---------------------------------------------------------------------------
// REAL channel-mix GEMM (bf16x3): out[b,o,p] = sum_k wr[o,k]*realF[b,k,p] + x.
// 2-stage cp.async pipeline; o-tiles fastest (F shared via L2).
// ---------------------------------------------------------------------------
#define SWS 40
#define SFS 136
#define STG 18944

__device__ __forceinline__ void cp16(void* sdst, const void* gsrc)
{
    unsigned sa = (unsigned)__cvta_generic_to_shared(sdst);
    asm volatile("cp.async.cg.shared.global [%0], [%1], 16;" :: "r"(sa), "l"(gsrc));
}
__device__ __forceinline__ void ldsm_x4(unsigned& r0, unsigned& r1, unsigned& r2, unsigned& r3,
                                        unsigned addr)
{
    asm volatile("ldmatrix.sync.aligned.m8n8.x4.shared.b16 {%0,%1,%2,%3}, [%4];"
                 : "=r"(r0), "=r"(r1), "=r"(r2), "=r"(r3) : "r"(addr));
}
__device__ __forceinline__ void ldsm_x4_t(unsigned& r0, unsigned& r1, unsigned& r2, unsigned& r3,
                                          unsigned addr)
{
    asm volatile("ldmatrix.sync.aligned.m8n8.x4.trans.shared.b16 {%0,%1,%2,%3}, [%4];"
                 : "=r"(r0), "=r"(r1), "=r"(r2), "=r"(r3) : "r"(addr));
}
__device__ __forceinline__ void mma16816(float* c, const unsigned* a, const unsigned* b)
{
    asm volatile("mma.sync.aligned.m16n8k16.row.col.f32.bf16.bf16.f32 "
                 "{%0,%1,%2,%3}, {%4,%5,%6,%7}, {%8,%9}, {%0,%1,%2,%3};"
                 : "+f"(c[0]), "+f"(c[1]), "+f"(c[2]), "+f"(c[3])
                 : "r"(a[0]), "r"(a[1]), "r"(a[2]), "r"(a[3]), "r"(b[0]), "r"(b[1]));
}

__global__ void __launch_bounds__(256) k_gemm_tc(const float* __restrict__ x,
                                                 float* __restrict__ out)
{
    extern __shared__ __nv_bfloat16 dsm[];

    const int b     = blockIdx.z;
    const int oBase = blockIdx.x * 128;   // fastest dim: o
    const int pBase = blockIdx.y * 128;
    const int tid   = threadIdx.x;
    const int lane  = tid & 31;
    const int warp  = tid >> 5;
    const int wo    = warp >> 1;
    const int wp    = warp & 1;

    const __nv_bfloat16* Fh = g_rfh + (size_t)b * NC * NPIX;
    const __nv_bfloat16* Fl = g_rfl + (size_t)b * NC * NPIX;

    float acc[2][8][4];
    #pragma unroll
    for (int m = 0; m < 2; ++m)
        #pragma unroll
        for (int n = 0; n < 8; ++n)
            #pragma unroll
            for (int q = 0; q < 4; ++q) acc[m][n][q] = 0.0f;

    const int aRow  = lane & 15;
    const int aKof  = (lane >> 4) << 3;
    const int bKrow = lane & 15;
    const int bPof  = (lane >> 4) << 3;

    auto issue_loads = [&](int s, int k0) {
        __nv_bfloat16* wbase = dsm + s*STG;
        #pragma unroll
        for (int t = 0; t < 4; ++t) {
            int id   = tid + t*256;
            int half = id >> 9;
            int cid  = id & 511;
            int o    = cid >> 2, kc = (cid & 3) << 3;
            const __nv_bfloat16* g = (half ? g_wrlo : g_wrhi) + (oBase + o)*NC + k0 + kc;
            cp16(wbase + half*128*SWS + o*SWS + kc, g);
        }
        __nv_bfloat16* fbase = dsm + s*STG + 2*128*SWS;
        #pragma unroll
        for (int t = 0; t < 4; ++t) {
            int id   = tid + t*256;
            int half = id >> 9;
            int cid  = id & 511;
            int k    = cid >> 4, pc = (cid & 15) << 3;
            const __nv_bfloat16* g = (half ? Fl : Fh) + (size_t)(k0 + k)*NPIX + pBase + pc;
            cp16(fbase + half*32*SFS + k*SFS + pc, g);
        }
        asm volatile("cp.async.commit_group;");
    };

    issue_loads(0, 0);

    const unsigned smem0 = (unsigned)__cvta_generic_to_shared(dsm);

    #pragma unroll 1
    for (int it = 0; it < 8; ++it) {
        if (it + 1 < 8) issue_loads((it + 1) & 1, (it + 1)*32);
        if (it + 1 < 8) asm volatile("cp.async.wait_group 1;");
        else            asm volatile("cp.async.wait_group 0;");
        __syncthreads();

        const unsigned base = smem0 + ((it & 1) ? STG*2u : 0u);
        const unsigned swh = base;
        const unsigned swl = base + 128*SWS*2;
        const unsigned sfh = base + 2*128*SWS*2;
        const unsigned sfl = sfh + 32*SFS*2;

        #pragma unroll
        for (int kk = 0; kk < 32; kk += 16) {
            unsigned ah[2][4], al[2][4];
            #pragma unroll
            for (int mt = 0; mt < 2; ++mt) {
                unsigned off = ((wo*32 + mt*16 + aRow)*SWS + kk + aKof) * 2;
                ldsm_x4(ah[mt][0], ah[mt][1], ah[mt][2], ah[mt][3], swh + off);
                ldsm_x4(al[mt][0], al[mt][1], al[mt][2], al[mt][3], swl + off);
            }
            unsigned bh[8][2], bl[8][2];
            #pragma unroll
            for (int ng = 0; ng < 4; ++ng) {
                unsigned off = ((kk + bKrow)*SFS + wp*64 + ng*16 + bPof) * 2;
                ldsm_x4_t(bh[2*ng][0], bh[2*ng][1], bh[2*ng+1][0], bh[2*ng+1][1], sfh + off);
                ldsm_x4_t(bl[2*ng][0], bl[2*ng][1], bl[2*ng+1][0], bl[2*ng+1][1], sfl + off);
            }
            #pragma unroll
            for (int mt = 0; mt < 2; ++mt)
                #pragma unroll
                for (int nt = 0; nt < 8; ++nt) {
                    mma16816(acc[mt][nt], ah[mt], bh[nt]);
                    mma16816(acc[mt][nt], ah[mt], bl[nt]);
                    mma16816(acc[mt][nt], al[mt], bh[nt]);
                }
        }
        __syncthreads();
    }

    const float* xb = x   + (size_t)b * NC * NPIX;
    float*       ob = out + (size_t)b * NC * NPIX;
    const int cRow = lane >> 2;
    const int cCol = (lane & 3) << 1;
    #pragma unroll
    for (int mt = 0; mt < 2; ++mt) {
        #pragma unroll
        for (int nt = 0; nt < 8; ++nt) {
            size_t o0 = (size_t)(oBase + wo*32 + mt*16 + cRow);
            size_t p  = (size_t)(pBase + wp*64 + nt*8 + cCol);
            float2 xv0 = *(const float2*)&xb[o0*NPIX + p];
            float2 xv1 = *(const float2*)&xb[(o0+8)*NPIX + p];
            *(float2*)&ob[o0*NPIX + p]     = make_float2(acc[mt][nt][0] + xv0.x,
                                                          acc[mt][nt][1] + xv0.y);
            *(float2*)&ob[(o0+8)*NPIX + p] = make_float2(acc[mt][nt][2] + xv1.x,
                                                          acc[mt][nt][3] + xv1.y);
        }
    }
}

// ---------------------------------------------------------------------------
extern "C" void kernel_launch(void* const* d_in, const int* in_sizes, int n_in,
                              void* d_out, int out_size)
{
    (void)in_sizes; (void)n_in; (void)out_size;
    const float* x  = (const float*)d_in[0];
    const float* w1 = (const float*)d_in[1];
    const float* b1 = (const float*)d_in[2];
    const float* w2 = (const float*)d_in[3];
    const float* b2 = (const float*)d_in[4];
    const float* wr = (const float*)d_in[5];
    float* out = (float*)d_out;

    cudaFuncSetAttribute(k_fftconv, cudaFuncAttributeMaxDynamicSharedMemorySize, FC_SMEM);
    cudaFuncSetAttribute(k_ifft,    cudaFuncAttributeMaxDynamicSharedMemorySize, FFT_SMEM);
    cudaFuncSetAttribute(k_gemm_tc, cudaFuncAttributeMaxDynamicSharedMemorySize, 2*STG*2);

    k_prep<<<NC*NC/256, 256>>>(wr);
    k_headg<<<NIMG, 128>>>(x);
    k_headmlp<<<NB, 64>>>(w1, b1, w2, b2);
    k_fftconv<<<NIMG/2, 1024, FC_SMEM>>>(x);
    k_ifft<<<NIMG/2, 1024, FFT_SMEM>>>();
    k_gemm_tc<<<dim3(NC/128, NPIX/128, NB), 256, 2*STG*2>>>(x, out);
}

// round 16
// speedup vs baseline: 1.5238x; 1.5238x over previous
#include <cuda_runtime.h>
#include <cuda_fp16.h>
#include <math.h>

// ---------------------------------------------------------------------------
// AFEModule, reordered (mix commutes with ifft):
// fft2 -> head -> conv (fp16 out) -> ifft (fp16 real field) -> real GEMM (+x).
// ---------------------------------------------------------------------------

#define NB    8
#define NC    256
#define NIMG  2048
#define HW    128
#define NPIX  16384
#define LDS_  129            // float2 plane stride (conflict-free)
#define PLANE 16512          // 128*129 float2 elements

#define FFT_SMEM (PLANE*8 + 512)

#define CP    134            // conv padded rows
#define CPS   136            // conv padded row stride
#define CONV_SMEM (CP*CPS*4) // one plane per CTA (72.9 KB)

// Scratch (device globals; allocation-free contract).
__device__ __align__(256) float  g_xf[NIMG * (size_t)NPIX * 2];   // fwd spectra, planar [img][re|im]
__device__ __align__(256) __half g_fc[NIMG * (size_t)NPIX * 2];   // conv out fp16, planar
__device__ __align__(256) __half g_rf[NIMG * (size_t)NPIX];       // real field fp16 (post-ifft)
__device__ __align__(16)  __half g_wrhi[NC * NC];
__device__ __align__(16)  __half g_wrlo[NC * NC];
__device__ float g_kern[NB * 49];

__device__ __forceinline__ int brev7(int v) { return (int)(__brev((unsigned)v) >> 25); }

// ---------------------------------------------------------------------------
// 1-D DIF FFT over 128 lines on an interleaved float2 plane.
// Round 1: radix-8 (stages 6,5,4). Round 2: radix-16 (stages 3,2,1,0).
// ---------------------------------------------------------------------------
__device__ void fft_pass(float2* sd, const float* twr, const float* twi,
                         int lineStride, int elemStride)
{
    for (int u = threadIdx.x; u < 2048; u += blockDim.x) {
        const int line = u & 127;
        const int j    = u >> 7;                  // 0..15
        const int o0   = line * lineStride + j * elemStride;
        const int st   = 16 * elemStride;
        float r[8], m[8];
        #pragma unroll
        for (int i = 0; i < 8; ++i) {
            float2 v = sd[o0 + i*st];
            r[i] = v.x; m[i] = v.y;
        }
        #pragma unroll
        for (int i = 0; i < 4; ++i) {
            float tr = r[i] + r[i+4], tm = m[i] + m[i+4];
            float dr = r[i] - r[i+4], dm = m[i] - m[i+4];
            const int e = j + 16*i;
            float wr_ = twr[e], wi_ = twi[e];
            r[i] = tr; m[i] = tm;
            r[i+4] = dr*wr_ - dm*wi_; m[i+4] = dr*wi_ + dm*wr_;
        }
        #pragma unroll
        for (int b2 = 0; b2 < 8; b2 += 4) {
            #pragma unroll
            for (int i = 0; i < 2; ++i) {
                const int a = b2 + i, bb = a + 2;
                float tr = r[a] + r[bb], tm = m[a] + m[bb];
                float dr = r[a] - r[bb], dm = m[a] - m[bb];
                const int e = 2*(j + 16*i);
                float wr_ = twr[e], wi_ = twi[e];
                r[a] = tr; m[a] = tm;
                r[bb] = dr*wr_ - dm*wi_; m[bb] = dr*wi_ + dm*wr_;
            }
        }
        {
            float wr_ = twr[4*j], wi_ = twi[4*j];
            #pragma unroll
            for (int a = 0; a < 8; a += 2) {
                float tr = r[a] + r[a+1], tm = m[a] + m[a+1];
                float dr = r[a] - r[a+1], dm = m[a] - m[a+1];
                r[a] = tr; m[a] = tm;
                r[a+1] = dr*wr_ - dm*wi_; m[a+1] = dr*wi_ + dm*wr_;
            }
        }
        #pragma unroll
        for (int i = 0; i < 8; ++i) sd[o0 + i*st] = make_float2(r[i], m[i]);
    }
    __syncthreads();

    for (int u = threadIdx.x; u < 1024; u += blockDim.x) {
        const int line = u & 127;
        const int g    = u >> 7;                  // 0..7
        const int o0   = line * lineStride + (g << 4) * elemStride;
        float r[16], m[16];
        #pragma unroll
        for (int i = 0; i < 16; ++i) {
            float2 v = sd[o0 + i*elemStride];
            r[i] = v.x; m[i] = v.y;
        }
        #pragma unroll
        for (int k = 0; k < 8; ++k) {
            float tr = r[k] + r[k+8], tm = m[k] + m[k+8];
            float dr = r[k] - r[k+8], dm = m[k] - m[k+8];
            float wr_ = twr[8*k], wi_ = twi[8*k];
            r[k] = tr; m[k] = tm;
            r[k+8] = dr*wr_ - dm*wi_; m[k+8] = dr*wi_ + dm*wr_;
        }
        #pragma unroll
        for (int b2 = 0; b2 < 16; b2 += 8) {
            #pragma unroll
            for (int i = 0; i < 4; ++i) {
                const int a = b2 + i, bb = a + 4;
                float tr = r[a] + r[bb], tm = m[a] + m[bb];
                float dr = r[a] - r[bb], dm = m[a] - m[bb];
                float wr_ = twr[16*i], wi_ = twi[16*i];
                r[a] = tr; m[a] = tm;
                r[bb] = dr*wr_ - dm*wi_; m[bb] = dr*wi_ + dm*wr_;
            }
        }
        #pragma unroll
        for (int b2 = 0; b2 < 16; b2 += 4) {
            #pragma unroll
            for (int i = 0; i < 2; ++i) {
                const int a = b2 + i, bb = a + 2;
                float tr = r[a] + r[bb], tm = m[a] + m[bb];
                float dr = r[a] - r[bb], dm = m[a] - m[bb];
                float wr_ = twr[32*i], wi_ = twi[32*i];
                r[a] = tr; m[a] = tm;
                r[bb] = dr*wr_ - dm*wi_; m[bb] = dr*wi_ + dm*wr_;
            }
        }
        #pragma unroll
        for (int a = 0; a < 16; a += 2) {
            float tr = r[a] + r[a+1], tm = m[a] + m[a+1];
            float dr = r[a] - r[a+1], dm = m[a] - m[a+1];
            r[a] = tr; m[a] = tm; r[a+1] = dr; m[a+1] = dm;
        }
        #pragma unroll
        for (int i = 0; i < 16; ++i) sd[o0 + i*elemStride] = make_float2(r[i], m[i]);
    }
    __syncthreads();
}

// ---------------------------------------------------------------------------
// Forward FFT2 (ortho) of TWO real images packed as x1 + i*x2.
// Separation per output with 4-wide vectorized coalesced stores.
// ---------------------------------------------------------------------------
__global__ void k_fft_fwd(const float* __restrict__ x)
{
    extern __shared__ float smraw[];
    float2* sd  = (float2*)smraw;
    float*  twr = smraw + 2*PLANE;
    float*  twi = twr + 64;

    const int ia = 2*blockIdx.x;
    const float4* x1 = (const float4*)(x + (size_t)ia * NPIX);
    const float4* x2 = (const float4*)(x + (size_t)(ia+1) * NPIX);

    for (int t = threadIdx.x; t < 64; t += blockDim.x) {
        float sv, cv;
        sincosf(-6.283185307179586f * (float)t / 128.0f, &sv, &cv);
        twr[t] = cv; twi[t] = sv;
    }
    for (int i = threadIdx.x; i < NPIX/4; i += blockDim.x) {
        int y = i >> 5, x4 = (i & 31) << 2;
        float4 a = x1[i], b = x2[i];
        float2* d = &sd[y*LDS_ + x4];
        d[0] = make_float2(a.x, b.x);
        d[1] = make_float2(a.y, b.y);
        d[2] = make_float2(a.z, b.z);
        d[3] = make_float2(a.w, b.w);
    }
    __syncthreads();

    fft_pass(sd, twr, twi, LDS_, 1);
    fft_pass(sd, twr, twi, 1, LDS_);

    float* d1 = g_xf + (size_t)ia * 2*NPIX;    // [re][im] planes
    float* d2 = d1 + 2*NPIX;
    const float sc = 1.0f / 128.0f;
    for (int idx = threadIdx.x; idx < 4096; idx += blockDim.x) {
        const int u  = idx >> 5;
        const int v0 = (idx & 31) << 2;
        const int bu  = brev7(u) * LDS_;
        const int bun = brev7((128 - u) & 127) * LDS_;
        float o1r[4], o1i[4], o2r[4], o2i[4];
        #pragma unroll
        for (int t = 0; t < 4; ++t) {
            const int v  = v0 + t;
            const int vn = (128 - v) & 127;
            float2 W = sd[bu  + brev7(v)];
            float2 N = sd[bun + brev7(vn)];
            o1r[t] = 0.5f*(W.x + N.x) * sc;
            o1i[t] = 0.5f*(W.y - N.y) * sc;
            o2r[t] = 0.5f*(W.y + N.y) * sc;
            o2i[t] = -0.5f*(W.x - N.x) * sc;
        }
        const int si = ((u+64)&127)*128 + ((v0+64)&127);
        *(float4*)&d1[si]        = make_float4(o1r[0], o1r[1], o1r[2], o1r[3]);
        *(float4*)&d1[NPIX + si] = make_float4(o1i[0], o1i[1], o1i[2], o1i[3]);
        *(float4*)&d2[si]        = make_float4(o2r[0], o2r[1], o2r[2], o2r[3]);
        *(float4*)&d2[NPIX + si] = make_float4(o2i[0], o2i[1], o2i[2], o2i[3]);
    }
}

// ---------------------------------------------------------------------------
__global__ void k_head(const float* __restrict__ w1, const float* __restrict__ b1,
                       const float* __restrict__ w2, const float* __restrict__ b2)
{
    __shared__ float center[49];
    __shared__ float hid[32];
    __shared__ float par[3];
    __shared__ float kk[50];

    const int b = blockIdx.x;
    const int tid  = threadIdx.x;
    const int lane = tid & 31;
    const int warp = tid >> 5;

    for (int p = warp; p < 49; p += 8) {
        const int h = 61 + p / 7, w = 61 + p % 7;
        float s = 0.0f;
        for (int c = lane; c < NC; c += 32) {
            const float* base = g_xf + ((size_t)b * NC + c) * 2*NPIX;
            float re = base[h*128 + w];
            float im = base[NPIX + h*128 + w];
            s += sqrtf(re*re + im*im);
        }
        #pragma unroll
        for (int o = 16; o; o >>= 1) s += __shfl_down_sync(0xFFFFFFFFu, s, o);
        if (lane == 0) center[p] = s * (1.0f / 256.0f);
    }
    __syncthreads();

    if (tid < 32) {
        float acc = b1[tid];
        for (int p = 0; p < 49; ++p) acc += center[p] * w1[p*32 + tid];
        hid[tid] = fmaxf(acc, 0.0f);
    }
    __syncthreads();
    if (tid < 3) {
        float acc = b2[tid];
        for (int j = 0; j < 32; ++j) acc += hid[j] * w2[j*3 + tid];
        par[tid] = acc;
    }
    __syncthreads();
    if (tid < 49) {
        float theta = atan2f(par[0], par[1]) * 0.5f + 1.5707963267948966f;
        float lam1  = expf(par[2]);
        float lam2  = 1.0f / (lam1 + 1e-8f);
        float ct, st;
        sincosf(theta, &st, &ct);
        float yy = (float)(tid / 7) - 3.0f;
        float xx = (float)(tid % 7) - 3.0f;
        float xr =  xx*ct + yy*st;
        float yr = -xx*st + yy*ct;
        kk[tid] = expf(-(xr*xr / (2.0f*lam1*lam1) + yr*yr / (2.0f*lam2*lam2)));
    }
    __syncthreads();
    if (tid == 0) {
        float s = 0.0f;
        for (int i = 0; i < 49; ++i) s += kk[i];
        kk[49] = s + 1e-8f;
    }
    __syncthreads();
    if (tid < 49) g_kern[b*49 + tid] = kk[tid] / kk[49];
}

// ---------------------------------------------------------------------------
__global__ void k_prep(const float* __restrict__ wr)
{
    int i = blockIdx.x * 256 + threadIdx.x;
    float v = wr[i];
    __half h = __float2half(v);
    g_wrhi[i] = h;
    g_wrlo[i] = __float2half(v - __half2float(h));
}

// ---------------------------------------------------------------------------
// 7x7 zero-pad conv, ONE plane per CTA (grid = (2, NIMG)); 512 thr, 4x8 tiles.
// float4 global loads; output single fp16, uint4-packed stores.
// ---------------------------------------------------------------------------
__global__ void __launch_bounds__(512) k_conv()
{
    extern __shared__ float sp[];
    __shared__ float kk[49];

    const int plane = blockIdx.x;     // 0 = re, 1 = im
    const int img   = blockIdx.y;
    const int b     = img >> 8;
    const int tid   = threadIdx.x;

    if (tid < 49) kk[tid] = g_kern[b*49 + tid];
    for (int i = tid; i < CP*CPS/4; i += 512) ((float4*)sp)[i] = make_float4(0,0,0,0);
    __syncthreads();

    const float4* src4 = (const float4*)(g_xf + ((size_t)img * 2 + plane) * NPIX);
    for (int i = tid; i < NPIX/4; i += 512) {
        int y = i >> 5, x4 = (i & 31) << 2;
        float4 v = src4[i];
        float* d = &sp[(y+3)*CPS + x4 + 3];
        d[0] = v.x; d[1] = v.y; d[2] = v.z; d[3] = v.w;
    }
    __syncthreads();

    const int y0 = (tid >> 4) << 2;   // 0..124
    const int x0 = (tid & 15) << 3;   // 0..120

    float acc[4][8];
    #pragma unroll
    for (int r = 0; r < 4; ++r)
        #pragma unroll
        for (int p = 0; p < 8; ++p) acc[r][p] = 0.0f;

    #pragma unroll
    for (int ri = 0; ri < 10; ++ri) {
        const float* pr = &sp[(y0 + ri)*CPS + x0];
        float buf[16];
        *(float4*)&buf[0]  = *(const float4*)&pr[0];
        *(float4*)&buf[4]  = *(const float4*)&pr[4];
        *(float4*)&buf[8]  = *(const float4*)&pr[8];
        *(float4*)&buf[12] = *(const float4*)&pr[12];
        #pragma unroll
        for (int r = 0; r < 4; ++r) {
            const int dy = ri - r;
            if (dy < 0 || dy > 6) continue;
            #pragma unroll
            for (int dx = 0; dx < 7; ++dx) {
                float w = kk[dy*7 + dx];
                #pragma unroll
                for (int p = 0; p < 8; ++p)
                    acc[r][p] = fmaf(w, buf[dx+p], acc[r][p]);
            }
        }
    }

    __half* dc = g_fc + ((size_t)img * 2 + plane) * NPIX;
    #pragma unroll
    for (int r = 0; r < 4; ++r) {
        const int o = (y0 + r)*128 + x0;
        uint4 pk;
        __half* hp = (__half*)&pk;
        #pragma unroll
        for (int p = 0; p < 8; ++p) hp[p] = __float2half(acc[r][p]);
        *(uint4*)&dc[o] = pk;
    }
}

// ---------------------------------------------------------------------------
// Inverse FFT2 (ortho) of TWO channels of conv output (fp16, Hermitian-
// projected, packed; dedup form). Emits real field fp16.
// ---------------------------------------------------------------------------
__global__ void k_ifft()
{
    extern __shared__ float smraw[];
    float2* sd  = (float2*)smraw;
    float*  twr = smraw + 2*PLANE;
    float*  twi = twr + 64;

    const int ia = 2*blockIdx.x;
    const __half* C1r = g_fc + (size_t)(2*ia + 0)*NPIX;
    const __half* C1i = g_fc + (size_t)(2*ia + 1)*NPIX;
    const __half* C2r = g_fc + (size_t)(2*ia + 2)*NPIX;
    const __half* C2i = g_fc + (size_t)(2*ia + 3)*NPIX;

    for (int t = threadIdx.x; t < 64; t += blockDim.x) {
        float sv, cv;
        sincosf(6.283185307179586f * (float)t / 128.0f, &sv, &cv);
        twr[t] = cv; twi[t] = sv;
    }
    for (int i = threadIdx.x; i < NPIX; i += blockDim.x) {
        const int u = i >> 7, v = i & 127;
        const int un = (128 - u) & 127, vn = (128 - v) & 127;
        const int j = un*128 + vn;
        if (i > j) continue;
        const int si = ((u+64)&127)*128 + ((v+64)&127);
        const int sj = ((un+64)&127)*128 + ((vn+64)&127);
        float A1r = __half2float(C1r[si]), B1r = __half2float(C1r[sj]);
        float A1i = __half2float(C1i[si]), B1i = __half2float(C1i[sj]);
        float A2r = __half2float(C2r[si]), B2r = __half2float(C2r[sj]);
        float A2i = __half2float(C2i[si]), B2i = __half2float(C2i[sj]);
        float r1 = 0.5f*(A1r + B1r), m1 = 0.5f*(A1i - B1i);
        float r2 = 0.5f*(A2r + B2r), m2 = 0.5f*(A2i - B2i);
        sd[u*LDS_ + v]   = make_float2(r1 - m2, m1 + r2);
        sd[un*LDS_ + vn] = make_float2(r1 + m2, r2 - m1);
    }
    __syncthreads();

    fft_pass(sd, twr, twi, LDS_, 1);
    fft_pass(sd, twr, twi, 1, LDS_);

    __half* h1 = g_rf + (size_t)ia * NPIX;
    __half* h2 = h1 + NPIX;
    const float sc = 1.0f / 128.0f;
    for (int i = threadIdx.x; i < NPIX; i += blockDim.x) {
        int u = i >> 7, v = i & 127;
        float2 s = sd[brev7(u)*LDS_ + brev7(v)];
        h1[i] = __float2half(s.x * sc);
        h2[i] = __float2half(s.y * sc);
    }
}

// ---------------------------------------------------------------------------
// REAL channel-mix GEMM (fp16 tensor cores, wr split hi/lo -> 2 MMAs):
// out[b,o,p] = sum_k wr[o,k]*realF[b,k,p] + x.
// 2-stage cp.async pipeline; o-tiles fastest (F shared via L2).
// ---------------------------------------------------------------------------
#define SWS 40
#define SFS 136
#define STG 14592   // halves per stage: 2*128*SWS + 32*SFS

__device__ __forceinline__ void cp16(void* sdst, const void* gsrc)
{
    unsigned sa = (unsigned)__cvta_generic_to_shared(sdst);
    asm volatile("cp.async.cg.shared.global [%0], [%1], 16;" :: "r"(sa), "l"(gsrc));
}
__device__ __forceinline__ void ldsm_x4(unsigned& r0, unsigned& r1, unsigned& r2, unsigned& r3,
                                        unsigned addr)
{
    asm volatile("ldmatrix.sync.aligned.m8n8.x4.shared.b16 {%0,%1,%2,%3}, [%4];"
                 : "=r"(r0), "=r"(r1), "=r"(r2), "=r"(r3) : "r"(addr));
}
__device__ __forceinline__ void ldsm_x4_t(unsigned& r0, unsigned& r1, unsigned& r2, unsigned& r3,
                                          unsigned addr)
{
    asm volatile("ldmatrix.sync.aligned.m8n8.x4.trans.shared.b16 {%0,%1,%2,%3}, [%4];"
                 : "=r"(r0), "=r"(r1), "=r"(r2), "=r"(r3) : "r"(addr));
}
__device__ __forceinline__ void mma16816(float* c, const unsigned* a, const unsigned* b)
{
    asm volatile("mma.sync.aligned.m16n8k16.row.col.f32.f16.f16.f32 "
                 "{%0,%1,%2,%3}, {%4,%5,%6,%7}, {%8,%9}, {%0,%1,%2,%3};"
                 : "+f"(c[0]), "+f"(c[1]), "+f"(c[2]), "+f"(c[3])
                 : "r"(a[0]), "r"(a[1]), "r"(a[2]), "r"(a[3]), "r"(b[0]), "r"(b[1]));
}

__global__ void __launch_bounds__(256) k_gemm_tc(const float* __restrict__ x,
                                                 float* __restrict__ out)
{
    extern __shared__ __half dsm[];

    const int b     = blockIdx.z;
    const int oBase = blockIdx.x * 128;   // fastest dim: o
    const int pBase = blockIdx.y * 128;
    const int tid   = threadIdx.x;
    const int lane  = tid & 31;
    const int warp  = tid >> 5;
    const int wo    = warp >> 1;
    const int wp    = warp & 1;

    const __half* F = g_rf + (size_t)b * NC * NPIX;

    float acc[2][8][4];
    #pragma unroll
    for (int m = 0; m < 2; ++m)
        #pragma unroll
        for (int n = 0; n < 8; ++n)
            #pragma unroll
            for (int q = 0; q < 4; ++q) acc[m][n][q] = 0.0f;

    const int aRow  = lane & 15;
    const int aKof  = (lane >> 4) << 3;
    const int bKrow = lane & 15;
    const int bPof  = (lane >> 4) << 3;

    auto issue_loads = [&](int s, int k0) {
        __half* wbase = dsm + s*STG;
        #pragma unroll
        for (int t = 0; t < 4; ++t) {
            int id   = tid + t*256;
            int half_ = id >> 9;
            int cid  = id & 511;
            int o    = cid >> 2, kc = (cid & 3) << 3;
            const __half* g = (half_ ? g_wrlo : g_wrhi) + (oBase + o)*NC + k0 + kc;
            cp16(wbase + half_*128*SWS + o*SWS + kc, g);
        }
        __half* fbase = dsm + s*STG + 2*128*SWS;
        #pragma unroll
        for (int t = 0; t < 2; ++t) {
            int id = tid + t*256;           // 0..511
            int k  = id >> 4, pc = (id & 15) << 3;
            cp16(fbase + k*SFS + pc, F + (size_t)(k0 + k)*NPIX + pBase + pc);
        }
        asm volatile("cp.async.commit_group;");
    };

    issue_loads(0, 0);

    const unsigned smem0 = (unsigned)__cvta_generic_to_shared(dsm);

    #pragma unroll 1
    for (int it = 0; it < 8; ++it) {
        if (it + 1 < 8) issue_loads((it + 1) & 1, (it + 1)*32);
        if (it + 1 < 8) asm volatile("cp.async.wait_group 1;");
        else            asm volatile("cp.async.wait_group 0;");
        __syncthreads();

        const unsigned base = smem0 + ((it & 1) ? STG*2u : 0u);
        const unsigned swh = base;
        const unsigned swl = base + 128*SWS*2;
        const unsigned sfp = base + 2*128*SWS*2;

        #pragma unroll
        for (int kk = 0; kk < 32; kk += 16) {
            unsigned ah[2][4], al[2][4];
            #pragma unroll
            for (int mt = 0; mt < 2; ++mt) {
                unsigned off = ((wo*32 + mt*16 + aRow)*SWS + kk + aKof) * 2;
                ldsm_x4(ah[mt][0], ah[mt][1], ah[mt][2], ah[mt][3], swh + off);
                ldsm_x4(al[mt][0], al[mt][1], al[mt][2], al[mt][3], swl + off);
            }
            unsigned bf[8][2];
            #pragma unroll
            for (int ng = 0; ng < 4; ++ng) {
                unsigned off = ((kk + bKrow)*SFS + wp*64 + ng*16 + bPof) * 2;
                ldsm_x4_t(bf[2*ng][0], bf[2*ng][1], bf[2*ng+1][0], bf[2*ng+1][1], sfp + off);
            }
            #pragma unroll
            for (int mt = 0; mt < 2; ++mt)
                #pragma unroll
                for (int nt = 0; nt < 8; ++nt) {
                    mma16816(acc[mt][nt], ah[mt], bf[nt]);
                    mma16816(acc[mt][nt], al[mt], bf[nt]);
                }
        }
        __syncthreads();
    }

    const float* xb = x   + (size_t)b * NC * NPIX;
    float*       ob = out + (size_t)b * NC * NPIX;
    const int cRow = lane >> 2;
    const int cCol = (lane & 3) << 1;
    #pragma unroll
    for (int mt = 0; mt < 2; ++mt) {
        #pragma unroll
        for (int nt = 0; nt < 8; ++nt) {
            size_t o0 = (size_t)(oBase + wo*32 + mt*16 + cRow);
            size_t p  = (size_t)(pBase + wp*64 + nt*8 + cCol);
            float2 xv0 = *(const float2*)&xb[o0*NPIX + p];
            float2 xv1 = *(const float2*)&xb[(o0+8)*NPIX + p];
            *(float2*)&ob[o0*NPIX + p]     = make_float2(acc[mt][nt][0] + xv0.x,
                                                          acc[mt][nt][1] + xv0.y);
            *(float2*)&ob[(o0+8)*NPIX + p] = make_float2(acc[mt][nt][2] + xv1.x,
                                                          acc[mt][nt][3] + xv1.y);
        }
    }
}

// ---------------------------------------------------------------------------
extern "C" void kernel_launch(void* const* d_in, const int* in_sizes, int n_in,
                              void* d_out, int out_size)
{
    (void)in_sizes; (void)n_in; (void)out_size;
    const float* x  = (const float*)d_in[0];
    const float* w1 = (const float*)d_in[1];
    const float* b1 = (const float*)d_in[2];
    const float* w2 = (const float*)d_in[3];
    const float* b2 = (const float*)d_in[4];
    const float* wr = (const float*)d_in[5];
    float* out = (float*)d_out;

    cudaFuncSetAttribute(k_fft_fwd, cudaFuncAttributeMaxDynamicSharedMemorySize, FFT_SMEM);
    cudaFuncSetAttribute(k_ifft,    cudaFuncAttributeMaxDynamicSharedMemorySize, FFT_SMEM);
    cudaFuncSetAttribute(k_conv,    cudaFuncAttributeMaxDynamicSharedMemorySize, CONV_SMEM);
    cudaFuncSetAttribute(k_gemm_tc, cudaFuncAttributeMaxDynamicSharedMemorySize, 2*STG*2);

    k_prep<<<NC*NC/256, 256>>>(wr);
    k_fft_fwd<<<NIMG/2, 1024, FFT_SMEM>>>(x);
    k_head<<<NB, 256>>>(w1, b1, w2, b2);
    k_conv<<<dim3(2, NIMG), 512, CONV_SMEM>>>();
    k_ifft<<<NIMG/2, 1024, FFT_SMEM>>>();
    k_gemm_tc<<<dim3(NC/128, NPIX/128, NB), 256, 2*STG*2>>>(x, out);
}

// round 17
// speedup vs baseline: 1.6406x; 1.0767x over previous
#include <cuda_runtime.h>
#include <cuda_fp16.h>
#include <math.h>

// ---------------------------------------------------------------------------
// AFEModule, reordered (mix commutes with ifft):
// fft2 (fp16 spectra) -> head -> conv (fp16 out) -> ifft (fp16 real field)
// -> real fp16 tensor-core GEMM (+x epilogue).
// ---------------------------------------------------------------------------

#define NB    8
#define NC    256
#define NIMG  2048
#define HW    128
#define NPIX  16384
#define LDS_  129            // float2 plane stride (conflict-free)
#define PLANE 16512          // 128*129 float2 elements

#define FFT_SMEM (PLANE*8 + 512)

#define CP    134            // conv padded rows
#define CPS   136            // conv padded row stride
#define CONV_SMEM (CP*CPS*4) // one plane per CTA (72.9 KB)

// Scratch (device globals; allocation-free contract).
__device__ __align__(256) __half g_xf[NIMG * (size_t)NPIX * 2];   // fwd spectra fp16, planar [img][re|im]
__device__ __align__(256) __half g_fc[NIMG * (size_t)NPIX * 2];   // conv out fp16, planar
__device__ __align__(256) __half g_rf[NIMG * (size_t)NPIX];       // real field fp16 (post-ifft)
__device__ __align__(16)  __half g_wrhi[NC * NC];
__device__ __align__(16)  __half g_wrlo[NC * NC];
__device__ float g_kern[NB * 49];

__device__ __forceinline__ int brev7(int v) { return (int)(__brev((unsigned)v) >> 25); }

// ---------------------------------------------------------------------------
// 1-D DIF FFT over 128 lines on an interleaved float2 plane.
// Round 1: radix-8 (stages 6,5,4). Round 2: radix-16 (stages 3,2,1,0).
// ---------------------------------------------------------------------------
__device__ void fft_pass(float2* sd, const float* twr, const float* twi,
                         int lineStride, int elemStride)
{
    for (int u = threadIdx.x; u < 2048; u += blockDim.x) {
        const int line = u & 127;
        const int j    = u >> 7;                  // 0..15
        const int o0   = line * lineStride + j * elemStride;
        const int st   = 16 * elemStride;
        float r[8], m[8];
        #pragma unroll
        for (int i = 0; i < 8; ++i) {
            float2 v = sd[o0 + i*st];
            r[i] = v.x; m[i] = v.y;
        }
        #pragma unroll
        for (int i = 0; i < 4; ++i) {
            float tr = r[i] + r[i+4], tm = m[i] + m[i+4];
            float dr = r[i] - r[i+4], dm = m[i] - m[i+4];
            const int e = j + 16*i;
            float wr_ = twr[e], wi_ = twi[e];
            r[i] = tr; m[i] = tm;
            r[i+4] = dr*wr_ - dm*wi_; m[i+4] = dr*wi_ + dm*wr_;
        }
        #pragma unroll
        for (int b2 = 0; b2 < 8; b2 += 4) {
            #pragma unroll
            for (int i = 0; i < 2; ++i) {
                const int a = b2 + i, bb = a + 2;
                float tr = r[a] + r[bb], tm = m[a] + m[bb];
                float dr = r[a] - r[bb], dm = m[a] - m[bb];
                const int e = 2*(j + 16*i);
                float wr_ = twr[e], wi_ = twi[e];
                r[a] = tr; m[a] = tm;
                r[bb] = dr*wr_ - dm*wi_; m[bb] = dr*wi_ + dm*wr_;
            }
        }
        {
            float wr_ = twr[4*j], wi_ = twi[4*j];
            #pragma unroll
            for (int a = 0; a < 8; a += 2) {
                float tr = r[a] + r[a+1], tm = m[a] + m[a+1];
                float dr = r[a] - r[a+1], dm = m[a] - m[a+1];
                r[a] = tr; m[a] = tm;
                r[a+1] = dr*wr_ - dm*wi_; m[a+1] = dr*wi_ + dm*wr_;
            }
        }
        #pragma unroll
        for (int i = 0; i < 8; ++i) sd[o0 + i*st] = make_float2(r[i], m[i]);
    }
    __syncthreads();

    for (int u = threadIdx.x; u < 1024; u += blockDim.x) {
        const int line = u & 127;
        const int g    = u >> 7;                  // 0..7
        const int o0   = line * lineStride + (g << 4) * elemStride;
        float r[16], m[16];
        #pragma unroll
        for (int i = 0; i < 16; ++i) {
            float2 v = sd[o0 + i*elemStride];
            r[i] = v.x; m[i] = v.y;
        }
        #pragma unroll
        for (int k = 0; k < 8; ++k) {
            float tr = r[k] + r[k+8], tm = m[k] + m[k+8];
            float dr = r[k] - r[k+8], dm = m[k] - m[k+8];
            float wr_ = twr[8*k], wi_ = twi[8*k];
            r[k] = tr; m[k] = tm;
            r[k+8] = dr*wr_ - dm*wi_; m[k+8] = dr*wi_ + dm*wr_;
        }
        #pragma unroll
        for (int b2 = 0; b2 < 16; b2 += 8) {
            #pragma unroll
            for (int i = 0; i < 4; ++i) {
                const int a = b2 + i, bb = a + 4;
                float tr = r[a] + r[bb], tm = m[a] + m[bb];
                float dr = r[a] - r[bb], dm = m[a] - m[bb];
                float wr_ = twr[16*i], wi_ = twi[16*i];
                r[a] = tr; m[a] = tm;
                r[bb] = dr*wr_ - dm*wi_; m[bb] = dr*wi_ + dm*wr_;
            }
        }
        #pragma unroll
        for (int b2 = 0; b2 < 16; b2 += 4) {
            #pragma unroll
            for (int i = 0; i < 2; ++i) {
                const int a = b2 + i, bb = a + 2;
                float tr = r[a] + r[bb], tm = m[a] + m[bb];
                float dr = r[a] - r[bb], dm = m[a] - m[bb];
                float wr_ = twr[32*i], wi_ = twi[32*i];
                r[a] = tr; m[a] = tm;
                r[bb] = dr*wr_ - dm*wi_; m[bb] = dr*wi_ + dm*wr_;
            }
        }
        #pragma unroll
        for (int a = 0; a < 16; a += 2) {
            float tr = r[a] + r[a+1], tm = m[a] + m[a+1];
            float dr = r[a] - r[a+1], dm = m[a] - m[a+1];
            r[a] = tr; m[a] = tm; r[a+1] = dr; m[a+1] = dm;
        }
        #pragma unroll
        for (int i = 0; i < 16; ++i) sd[o0 + i*elemStride] = make_float2(r[i], m[i]);
    }
    __syncthreads();
}

// ---------------------------------------------------------------------------
// Forward FFT2 (ortho) of TWO real images packed as x1 + i*x2.
// Separation per output; fp16 planar store (4-half packets).
// ---------------------------------------------------------------------------
__global__ void k_fft_fwd(const float* __restrict__ x)
{
    extern __shared__ float smraw[];
    float2* sd  = (float2*)smraw;
    float*  twr = smraw + 2*PLANE;
    float*  twi = twr + 64;

    const int ia = 2*blockIdx.x;
    const float4* x1 = (const float4*)(x + (size_t)ia * NPIX);
    const float4* x2 = (const float4*)(x + (size_t)(ia+1) * NPIX);

    for (int t = threadIdx.x; t < 64; t += blockDim.x) {
        float sv, cv;
        sincosf(-6.283185307179586f * (float)t / 128.0f, &sv, &cv);
        twr[t] = cv; twi[t] = sv;
    }
    for (int i = threadIdx.x; i < NPIX/4; i += blockDim.x) {
        int y = i >> 5, x4 = (i & 31) << 2;
        float4 a = x1[i], b = x2[i];
        float2* d = &sd[y*LDS_ + x4];
        d[0] = make_float2(a.x, b.x);
        d[1] = make_float2(a.y, b.y);
        d[2] = make_float2(a.z, b.z);
        d[3] = make_float2(a.w, b.w);
    }
    __syncthreads();

    fft_pass(sd, twr, twi, LDS_, 1);
    fft_pass(sd, twr, twi, 1, LDS_);

    __half* d1 = g_xf + (size_t)ia * 2*NPIX;    // [re][im] planes
    __half* d2 = d1 + 2*NPIX;
    const float sc = 1.0f / 128.0f;
    for (int idx = threadIdx.x; idx < 4096; idx += blockDim.x) {
        const int u  = idx >> 5;
        const int v0 = (idx & 31) << 2;
        const int bu  = brev7(u) * LDS_;
        const int bun = brev7((128 - u) & 127) * LDS_;
        __half o1r[4], o1i[4], o2r[4], o2i[4];
        #pragma unroll
        for (int t = 0; t < 4; ++t) {
            const int v  = v0 + t;
            const int vn = (128 - v) & 127;
            float2 W = sd[bu  + brev7(v)];
            float2 N = sd[bun + brev7(vn)];
            o1r[t] = __float2half(0.5f*(W.x + N.x) * sc);
            o1i[t] = __float2half(0.5f*(W.y - N.y) * sc);
            o2r[t] = __float2half(0.5f*(W.y + N.y) * sc);
            o2i[t] = __float2half(-0.5f*(W.x - N.x) * sc);
        }
        const int si = ((u+64)&127)*128 + ((v0+64)&127);
        *(uint2*)&d1[si]        = *(uint2*)o1r;
        *(uint2*)&d1[NPIX + si] = *(uint2*)o1i;
        *(uint2*)&d2[si]        = *(uint2*)o2r;
        *(uint2*)&d2[NPIX + si] = *(uint2*)o2i;
    }
}

// ---------------------------------------------------------------------------
__global__ void k_head(const float* __restrict__ w1, const float* __restrict__ b1,
                       const float* __restrict__ w2, const float* __restrict__ b2)
{
    __shared__ float center[49];
    __shared__ float hid[32];
    __shared__ float par[3];
    __shared__ float kk[50];

    const int b = blockIdx.x;
    const int tid  = threadIdx.x;
    const int lane = tid & 31;
    const int warp = tid >> 5;

    for (int p = warp; p < 49; p += 8) {
        const int h = 61 + p / 7, w = 61 + p % 7;
        float s = 0.0f;
        for (int c = lane; c < NC; c += 32) {
            const __half* base = g_xf + ((size_t)b * NC + c) * 2*NPIX;
            float re = __half2float(base[h*128 + w]);
            float im = __half2float(base[NPIX + h*128 + w]);
            s += sqrtf(re*re + im*im);
        }
        #pragma unroll
        for (int o = 16; o; o >>= 1) s += __shfl_down_sync(0xFFFFFFFFu, s, o);
        if (lane == 0) center[p] = s * (1.0f / 256.0f);
    }
    __syncthreads();

    if (tid < 32) {
        float acc = b1[tid];
        for (int p = 0; p < 49; ++p) acc += center[p] * w1[p*32 + tid];
        hid[tid] = fmaxf(acc, 0.0f);
    }
    __syncthreads();
    if (tid < 3) {
        float acc = b2[tid];
        for (int j = 0; j < 32; ++j) acc += hid[j] * w2[j*3 + tid];
        par[tid] = acc;
    }
    __syncthreads();
    if (tid < 49) {
        float theta = atan2f(par[0], par[1]) * 0.5f + 1.5707963267948966f;
        float lam1  = expf(par[2]);
        float lam2  = 1.0f / (lam1 + 1e-8f);
        float ct, st;
        sincosf(theta, &st, &ct);
        float yy = (float)(tid / 7) - 3.0f;
        float xx = (float)(tid % 7) - 3.0f;
        float xr =  xx*ct + yy*st;
        float yr = -xx*st + yy*ct;
        kk[tid] = expf(-(xr*xr / (2.0f*lam1*lam1) + yr*yr / (2.0f*lam2*lam2)));
    }
    __syncthreads();
    if (tid == 0) {
        float s = 0.0f;
        for (int i = 0; i < 49; ++i) s += kk[i];
        kk[49] = s + 1e-8f;
    }
    __syncthreads();
    if (tid < 49) g_kern[b*49 + tid] = kk[tid] / kk[49];
}

// ---------------------------------------------------------------------------
__global__ void k_prep(const float* __restrict__ wr)
{
    int i = blockIdx.x * 256 + threadIdx.x;
    float v = wr[i];
    __half h = __float2half(v);
    g_wrhi[i] = h;
    g_wrlo[i] = __float2half(v - __half2float(h));
}

// ---------------------------------------------------------------------------
// 7x7 zero-pad conv, ONE plane per CTA (grid = (2, NIMG)); 512 thr, 4x8 tiles.
// fp16 input (uint4 = 8 halves per load), fp16 packed stores.
// ---------------------------------------------------------------------------
__global__ void __launch_bounds__(512) k_conv()
{
    extern __shared__ float sp[];
    __shared__ float kk[49];

    const int plane = blockIdx.x;     // 0 = re, 1 = im
    const int img   = blockIdx.y;
    const int b     = img >> 8;
    const int tid   = threadIdx.x;

    if (tid < 49) kk[tid] = g_kern[b*49 + tid];
    for (int i = tid; i < CP*CPS/4; i += 512) ((float4*)sp)[i] = make_float4(0,0,0,0);
    __syncthreads();

    const __half* src = g_xf + ((size_t)img * 2 + plane) * NPIX;
    for (int i = tid; i < NPIX/8; i += 512) {
        int y = i >> 4, x8 = (i & 15) << 3;
        uint4 pk = *(const uint4*)&src[y*128 + x8];
        const __half* hp = (const __half*)&pk;
        float* d = &sp[(y+3)*CPS + x8 + 3];
        #pragma unroll
        for (int p = 0; p < 8; ++p) d[p] = __half2float(hp[p]);
    }
    __syncthreads();

    const int y0 = (tid >> 4) << 2;   // 0..124
    const int x0 = (tid & 15) << 3;   // 0..120

    float acc[4][8];
    #pragma unroll
    for (int r = 0; r < 4; ++r)
        #pragma unroll
        for (int p = 0; p < 8; ++p) acc[r][p] = 0.0f;

    #pragma unroll
    for (int ri = 0; ri < 10; ++ri) {
        const float* pr = &sp[(y0 + ri)*CPS + x0];
        float buf[16];
        *(float4*)&buf[0]  = *(const float4*)&pr[0];
        *(float4*)&buf[4]  = *(const float4*)&pr[4];
        *(float4*)&buf[8]  = *(const float4*)&pr[8];
        *(float4*)&buf[12] = *(const float4*)&pr[12];
        #pragma unroll
        for (int r = 0; r < 4; ++r) {
            const int dy = ri - r;
            if (dy < 0 || dy > 6) continue;
            #pragma unroll
            for (int dx = 0; dx < 7; ++dx) {
                float w = kk[dy*7 + dx];
                #pragma unroll
                for (int p = 0; p < 8; ++p)
                    acc[r][p] = fmaf(w, buf[dx+p], acc[r][p]);
            }
        }
    }

    __half* dc = g_fc + ((size_t)img * 2 + plane) * NPIX;
    #pragma unroll
    for (int r = 0; r < 4; ++r) {
        const int o = (y0 + r)*128 + x0;
        uint4 pk;
        __half* hp = (__half*)&pk;
        #pragma unroll
        for (int p = 0; p < 8; ++p) hp[p] = __float2half(acc[r][p]);
        *(uint4*)&dc[o] = pk;
    }
}

// ---------------------------------------------------------------------------
// Inverse FFT2 (ortho) of TWO channels of conv output (fp16, Hermitian-
// projected, packed; dedup form). Emits real field fp16.
// ---------------------------------------------------------------------------
__global__ void k_ifft()
{
    extern __shared__ float smraw[];
    float2* sd  = (float2*)smraw;
    float*  twr = smraw + 2*PLANE;
    float*  twi = twr + 64;

    const int ia = 2*blockIdx.x;
    const __half* C1r = g_fc + (size_t)(2*ia + 0)*NPIX;
    const __half* C1i = g_fc + (size_t)(2*ia + 1)*NPIX;
    const __half* C2r = g_fc + (size_t)(2*ia + 2)*NPIX;
    const __half* C2i = g_fc + (size_t)(2*ia + 3)*NPIX;

    for (int t = threadIdx.x; t < 64; t += blockDim.x) {
        float sv, cv;
        sincosf(6.283185307179586f * (float)t / 128.0f, &sv, &cv);
        twr[t] = cv; twi[t] = sv;
    }
    for (int i = threadIdx.x; i < NPIX; i += blockDim.x) {
        const int u = i >> 7, v = i & 127;
        const int un = (128 - u) & 127, vn = (128 - v) & 127;
        const int j = un*128 + vn;
        if (i > j) continue;
        const int si = ((u+64)&127)*128 + ((v+64)&127);
        const int sj = ((un+64)&127)*128 + ((vn+64)&127);
        float A1r = __half2float(C1r[si]), B1r = __half2float(C1r[sj]);
        float A1i = __half2float(C1i[si]), B1i = __half2float(C1i[sj]);
        float A2r = __half2float(C2r[si]), B2r = __half2float(C2r[sj]);
        float A2i = __half2float(C2i[si]), B2i = __half2float(C2i[sj]);
        float r1 = 0.5f*(A1r + B1r), m1 = 0.5f*(A1i - B1i);
        float r2 = 0.5f*(A2r + B2r), m2 = 0.5f*(A2i - B2i);
        sd[u*LDS_ + v]   = make_float2(r1 - m2, m1 + r2);
        sd[un*LDS_ + vn] = make_float2(r1 + m2, r2 - m1);
    }
    __syncthreads();

    fft_pass(sd, twr, twi, LDS_, 1);
    fft_pass(sd, twr, twi, 1, LDS_);

    __half* h1 = g_rf + (size_t)ia * NPIX;
    __half* h2 = h1 + NPIX;
    const float sc = 1.0f / 128.0f;
    for (int i = threadIdx.x; i < NPIX; i += blockDim.x) {
        int u = i >> 7, v = i & 127;
        float2 s = sd[brev7(u)*LDS_ + brev7(v)];
        h1[i] = __float2half(s.x * sc);
        h2[i] = __float2half(s.y * sc);
    }
}

// ---------------------------------------------------------------------------
// REAL channel-mix GEMM (fp16 tensor cores, wr split hi/lo -> 2 MMAs):
// out[b,o,p] = sum_k wr[o,k]*realF[b,k,p] + x.
// ---------------------------------------------------------------------------
#define SWS 40
#define SFS 136
#define STG 14592   // halves per stage: 2*128*SWS + 32*SFS

__device__ __forceinline__ void cp16(void* sdst, const void* gsrc)
{
    unsigned sa = (unsigned)__cvta_generic_to_shared(sdst);
    asm volatile("cp.async.cg.shared.global [%0], [%1], 16;" :: "r"(sa), "l"(gsrc));
}
__device__ __forceinline__ void ldsm_x4(unsigned& r0, unsigned& r1, unsigned& r2, unsigned& r3,
                                        unsigned addr)
{
    asm volatile("ldmatrix.sync.aligned.m8n8.x4.shared.b16 {%0,%1,%2,%3}, [%4];"
                 : "=r"(r0), "=r"(r1), "=r"(r2), "=r"(r3) : "r"(addr));
}
__device__ __forceinline__ void ldsm_x4_t(unsigned& r0, unsigned& r1, unsigned& r2, unsigned& r3,
                                          unsigned addr)
{
    asm volatile("ldmatrix.sync.aligned.m8n8.x4.trans.shared.b16 {%0,%1,%2,%3}, [%4];"
                 : "=r"(r0), "=r"(r1), "=r"(r2), "=r"(r3) : "r"(addr));
}
__device__ __forceinline__ void mma16816(float* c, const unsigned* a, const unsigned* b)
{
    asm volatile("mma.sync.aligned.m16n8k16.row.col.f32.f16.f16.f32 "
                 "{%0,%1,%2,%3}, {%4,%5,%6,%7}, {%8,%9}, {%0,%1,%2,%3};"
                 : "+f"(c[0]), "+f"(c[1]), "+f"(c[2]), "+f"(c[3])
                 : "r"(a[0]), "r"(a[1]), "r"(a[2]), "r"(a[3]), "r"(b[0]), "r"(b[1]));
}

__global__ void __launch_bounds__(256) k_gemm_tc(const float* __restrict__ x,
                                                 float* __restrict__ out)
{
    extern __shared__ __half dsm[];

    const int b     = blockIdx.z;
    const int oBase = blockIdx.x * 128;   // fastest dim: o
    const int pBase = blockIdx.y * 128;
    const int tid   = threadIdx.x;
    const int lane  = tid & 31;
    const int warp  = tid >> 5;
    const int wo    = warp >> 1;
    const int wp    = warp & 1;

    const __half* F = g_rf + (size_t)b * NC * NPIX;

    float acc[2][8][4];
    #pragma unroll
    for (int m = 0; m < 2; ++m)
        #pragma unroll
        for (int n = 0; n < 8; ++n)
            #pragma unroll
            for (int q = 0; q < 4; ++q) acc[m][n][q] = 0.0f;

    const int aRow  = lane & 15;
    const int aKof  = (lane >> 4) << 3;
    const int bKrow = lane & 15;
    const int bPof  = (lane >> 4) << 3;

    auto issue_loads = [&](int s, int k0) {
        __half* wbase = dsm + s*STG;
        #pragma unroll
        for (int t = 0; t < 4; ++t) {
            int id   = tid + t*256;
            int half_ = id >> 9;
            int cid  = id & 511;
            int o    = cid >> 2, kc = (cid & 3) << 3;
            const __half* g = (half_ ? g_wrlo : g_wrhi) + (oBase + o)*NC + k0 + kc;
            cp16(wbase + half_*128*SWS + o*SWS + kc, g);
        }
        __half* fbase = dsm + s*STG + 2*128*SWS;
        #pragma unroll
        for (int t = 0; t < 2; ++t) {
            int id = tid + t*256;
            int k  = id >> 4, pc = (id & 15) << 3;
            cp16(fbase + k*SFS + pc, F + (size_t)(k0 + k)*NPIX + pBase + pc);
        }
        asm volatile("cp.async.commit_group;");
    };

    issue_loads(0, 0);

    const unsigned smem0 = (unsigned)__cvta_generic_to_shared(dsm);

    #pragma unroll 1
    for (int it = 0; it < 8; ++it) {
        if (it + 1 < 8) issue_loads((it + 1) & 1, (it + 1)*32);
        if (it + 1 < 8) asm volatile("cp.async.wait_group 1;");
        else            asm volatile("cp.async.wait_group 0;");
        __syncthreads();

        const unsigned base = smem0 + ((it & 1) ? STG*2u : 0u);
        const unsigned swh = base;
        const unsigned swl = base + 128*SWS*2;
        const unsigned sfp = base + 2*128*SWS*2;

        #pragma unroll
        for (int kk = 0; kk < 32; kk += 16) {
            unsigned ah[2][4], al[2][4];
            #pragma unroll
            for (int mt = 0; mt < 2; ++mt) {
                unsigned off = ((wo*32 + mt*16 + aRow)*SWS + kk + aKof) * 2;
                ldsm_x4(ah[mt][0], ah[mt][1], ah[mt][2], ah[mt][3], swh + off);
                ldsm_x4(al[mt][0], al[mt][1], al[mt][2], al[mt][3], swl + off);
            }
            unsigned bf[8][2];
            #pragma unroll
            for (int ng = 0; ng < 4; ++ng) {
                unsigned off = ((kk + bKrow)*SFS + wp*64 + ng*16 + bPof) * 2;
                ldsm_x4_t(bf[2*ng][0], bf[2*ng][1], bf[2*ng+1][0], bf[2*ng+1][1], sfp + off);
            }
            #pragma unroll
            for (int mt = 0; mt < 2; ++mt)
                #pragma unroll
                for (int nt = 0; nt < 8; ++nt) {
                    mma16816(acc[mt][nt], ah[mt], bf[nt]);
                    mma16816(acc[mt][nt], al[mt], bf[nt]);
                }
        }
        __syncthreads();
    }

    const float* xb = x   + (size_t)b * NC * NPIX;
    float*       ob = out + (size_t)b * NC * NPIX;
    const int cRow = lane >> 2;
    const int cCol = (lane & 3) << 1;
    #pragma unroll
    for (int mt = 0; mt < 2; ++mt) {
        #pragma unroll
        for (int nt = 0; nt < 8; ++nt) {
            size_t o0 = (size_t)(oBase + wo*32 + mt*16 + cRow);
            size_t p  = (size_t)(pBase + wp*64 + nt*8 + cCol);
            float2 xv0 = *(const float2*)&xb[o0*NPIX + p];
            float2 xv1 = *(const float2*)&xb[(o0+8)*NPIX + p];
            *(float2*)&ob[o0*NPIX + p]     = make_float2(acc[mt][nt][0] + xv0.x,
                                                          acc[mt][nt][1] + xv0.y);
            *(float2*)&ob[(o0+8)*NPIX + p] = make_float2(acc[mt][nt][2] + xv1.x,
                                                          acc[mt][nt][3] + xv1.y);
        }
    }
}

// ---------------------------------------------------------------------------
extern "C" void kernel_launch(void* const* d_in, const int* in_sizes, int n_in,
                              void* d_out, int out_size)
{
    (void)in_sizes; (void)n_in; (void)out_size;
    const float* x  = (const float*)d_in[0];
    const float* w1 = (const float*)d_in[1];
    const float* b1 = (const float*)d_in[2];
    const float* w2 = (const float*)d_in[3];
    const float* b2 = (const float*)d_in[4];
    const float* wr = (const float*)d_in[5];
    float* out = (float*)d_out;

    cudaFuncSetAttribute(k_fft_fwd, cudaFuncAttributeMaxDynamicSharedMemorySize, FFT_SMEM);
    cudaFuncSetAttribute(k_ifft,    cudaFuncAttributeMaxDynamicSharedMemorySize, FFT_SMEM);
    cudaFuncSetAttribute(k_conv,    cudaFuncAttributeMaxDynamicSharedMemorySize, CONV_SMEM);
    cudaFuncSetAttribute(k_gemm_tc, cudaFuncAttributeMaxDynamicSharedMemorySize, 2*STG*2);

    k_prep<<<NC*NC/256, 256>>>(wr);
    k_fft_fwd<<<NIMG/2, 1024, FFT_SMEM>>>(x);
    k_head<<<NB, 256>>>(w1, b1, w2, b2);
    k_conv<<<dim3(2, NIMG), 512, CONV_SMEM>>>();
    k_ifft<<<NIMG/2, 1024, FFT_SMEM>>>();
    k_gemm_tc<<<dim3(NC/128, NPIX/128, NB), 256, 2*STG*2>>>(x, out);
}